// round 1
// baseline (speedup 1.0000x reference)
#include <cuda_runtime.h>
#include <cuda_bf16.h>
#include <math_constants.h>

// Problem constants (fixed by the dataset)
#define NN   50000
#define FF   128
#define HH   4
#define CC   64
#define EE   400000
#define ETOT (EE + NN)          // edges + self loops = 450000
#define HC   (HH * CC)          // 256
#define NEG_SLOPE 0.2f

// Output layout: [action(1), h2(N*C), alpha2(ETOT), logits(N)]
#define OFF_ACTION 0
#define OFF_H2     1
#define OFF_ALPHA  (1 + NN * CC)
#define OFF_LOGITS (1 + NN * CC + ETOT)

// ---------------- scratch (static device globals; no allocation) ----------------
__device__ float    g_hfeat1[NN * HC];   // x @ W1
__device__ float    g_res1  [NN * HC];   // x @ W_res1
__device__ float    g_out1  [NN * HC];   // layer-1 aggregate -> becomes h1
__device__ float    g_asrc1 [NN * HH];
__device__ float    g_adst1 [NN * HH];
__device__ float    g_e1    [ETOT * HH];
__device__ float    g_sum1  [NN * HH];
__device__ unsigned g_max1  [NN * HH];

__device__ float    g_hfeat2[NN * CC];   // h1 @ W2
__device__ float    g_res2  [NN * CC];   // h1 @ W_res2
__device__ float    g_out2  [NN * CC];
__device__ float    g_asrc2 [NN];
__device__ float    g_adst2 [NN];
__device__ float    g_e2    [ETOT];
__device__ float    g_sum2  [NN];
__device__ unsigned g_max2  [NN];

#define NB_ARGMAX 196
__device__ float g_pval[NB_ARGMAX];
__device__ int   g_pidx[NB_ARGMAX];

// ---------------- helpers ----------------
__device__ __forceinline__ float wsum(float v) {
#pragma unroll
    for (int o = 16; o; o >>= 1) v += __shfl_xor_sync(0xffffffffu, v, o);
    return v;
}
// order-preserving float <-> uint for atomicMax on signed floats
__device__ __forceinline__ unsigned f2u(float f) {
    unsigned u = __float_as_uint(f);
    return (u & 0x80000000u) ? ~u : (u | 0x80000000u);
}
__device__ __forceinline__ float u2f(unsigned u) {
    return __uint_as_float((u & 0x80000000u) ? (u & 0x7fffffffu) : ~u);
}

// ---------------- init ----------------
__global__ void init_kernel() {
    int i = blockIdx.x * blockDim.x + threadIdx.x;
    int stride = gridDim.x * blockDim.x;
    for (int j = i; j < NN * HC; j += stride) g_out1[j] = 0.f;
    for (int j = i; j < NN * CC; j += stride) g_out2[j] = 0.f;
    for (int j = i; j < NN * HH; j += stride) { g_sum1[j] = 0.f; g_max1[j] = 0u; }
    for (int j = i; j < NN;      j += stride) { g_sum2[j] = 0.f; g_max2[j] = 0u; }
}

// ---------------- SGEMM: C[M,Nn] = A[M,K] @ B[K,Nn] (fp32) ----------------
// 64x64 tile, BK=16, 256 threads, 4x4 per thread. M guarded; K,Nn multiples of 16/64.
__global__ __launch_bounds__(256) void sgemm(const float* __restrict__ A,
                                             const float* __restrict__ B,
                                             float* __restrict__ C,
                                             int M, int K, int Nn) {
    __shared__ float As[16][64];
    __shared__ float Bs[16][64];
    const int tid = threadIdx.x;
    const int bm = blockIdx.y * 64, bn = blockIdx.x * 64;
    const int arow = tid >> 2, acol = (tid & 3) * 4;
    const int brow = tid >> 4, bcol = (tid & 15) * 4;
    const int tr = tid >> 4, tc = tid & 15;
    const bool arow_ok = (bm + arow) < M;
    float acc[4][4] = {};

    for (int k0 = 0; k0 < K; k0 += 16) {
        float4 av = arow_ok
            ? *(const float4*)&A[(size_t)(bm + arow) * K + k0 + acol]
            : make_float4(0.f, 0.f, 0.f, 0.f);
        As[acol + 0][arow] = av.x;
        As[acol + 1][arow] = av.y;
        As[acol + 2][arow] = av.z;
        As[acol + 3][arow] = av.w;
        *(float4*)&Bs[brow][bcol] = *(const float4*)&B[(size_t)(k0 + brow) * Nn + bn + bcol];
        __syncthreads();
#pragma unroll
        for (int kk = 0; kk < 16; kk++) {
            float a0 = As[kk][tr * 4 + 0];
            float a1 = As[kk][tr * 4 + 1];
            float a2 = As[kk][tr * 4 + 2];
            float a3 = As[kk][tr * 4 + 3];
            float b0 = Bs[kk][tc * 4 + 0];
            float b1 = Bs[kk][tc * 4 + 1];
            float b2 = Bs[kk][tc * 4 + 2];
            float b3 = Bs[kk][tc * 4 + 3];
            acc[0][0] += a0 * b0; acc[0][1] += a0 * b1; acc[0][2] += a0 * b2; acc[0][3] += a0 * b3;
            acc[1][0] += a1 * b0; acc[1][1] += a1 * b1; acc[1][2] += a1 * b2; acc[1][3] += a1 * b3;
            acc[2][0] += a2 * b0; acc[2][1] += a2 * b1; acc[2][2] += a2 * b2; acc[2][3] += a2 * b3;
            acc[3][0] += a3 * b0; acc[3][1] += a3 * b1; acc[3][2] += a3 * b2; acc[3][3] += a3 * b3;
        }
        __syncthreads();
    }
#pragma unroll
    for (int i = 0; i < 4; i++) {
        int row = bm + tr * 4 + i;
        if (row < M) {
            float4 v = make_float4(acc[i][0], acc[i][1], acc[i][2], acc[i][3]);
            *(float4*)&C[(size_t)row * Nn + bn + tc * 4] = v;
        }
    }
}

// ---------------- attention dot products ----------------
// warp per (node, head): a_src[n,h] = sum_c hfeat1[n,h,c]*att_src[h,c]
__global__ void attn1_kernel(const float* __restrict__ as, const float* __restrict__ ad) {
    int w = (blockIdx.x * blockDim.x + threadIdx.x) >> 5;
    int lane = threadIdx.x & 31;
    if (w >= NN * HH) return;
    int n = w >> 2, hh = w & 3;
    const float* hrow = &g_hfeat1[n * HC + hh * CC];
    float v0 = hrow[lane], v1 = hrow[lane + 32];
    float ps = v0 * as[hh * CC + lane] + v1 * as[hh * CC + lane + 32];
    float pd = v0 * ad[hh * CC + lane] + v1 * ad[hh * CC + lane + 32];
    ps = wsum(ps);
    pd = wsum(pd);
    if (lane == 0) { g_asrc1[w] = ps; g_adst1[w] = pd; }
}

// warp per node (heads=1)
__global__ void attn2_kernel(const float* __restrict__ as, const float* __restrict__ ad) {
    int n = (blockIdx.x * blockDim.x + threadIdx.x) >> 5;
    int lane = threadIdx.x & 31;
    if (n >= NN) return;
    const float* hrow = &g_hfeat2[n * CC];
    float v0 = hrow[lane], v1 = hrow[lane + 32];
    float ps = v0 * as[lane] + v1 * as[lane + 32];
    float pd = v0 * ad[lane] + v1 * ad[lane + 32];
    ps = wsum(ps);
    pd = wsum(pd);
    if (lane == 0) { g_asrc2[n] = ps; g_adst2[n] = pd; }
}

// ---------------- layer-1 edge passes ----------------
__device__ __forceinline__ void edge_sd(const int* __restrict__ ei, int ee, int& s, int& d) {
    if (ee < EE) { s = ei[ee]; d = ei[EE + ee]; }
    else         { s = d = ee - EE; }
}

__global__ void edge_a1(const int* __restrict__ ei) {
    int idx = blockIdx.x * blockDim.x + threadIdx.x;
    if (idx >= ETOT * HH) return;
    int ee = idx >> 2, hh = idx & 3;
    int s, d; edge_sd(ei, ee, s, d);
    float e = g_asrc1[s * HH + hh] + g_adst1[d * HH + hh];
    e = (e > 0.f) ? e : NEG_SLOPE * e;
    g_e1[idx] = e;
    atomicMax(&g_max1[d * HH + hh], f2u(e));
}

__global__ void edge_b1(const int* __restrict__ ei) {
    int idx = blockIdx.x * blockDim.x + threadIdx.x;
    if (idx >= ETOT * HH) return;
    int ee = idx >> 2, hh = idx & 3;
    int s, d; edge_sd(ei, ee, s, d);
    (void)s;
    float ex = __expf(g_e1[idx] - u2f(g_max1[d * HH + hh]));
    g_e1[idx] = ex;
    atomicAdd(&g_sum1[d * HH + hh], ex);
}

// warp per edge; scatter h[src]*alpha into out1[dst]
__global__ void edge_c1(const int* __restrict__ ei) {
    int w = (blockIdx.x * blockDim.x + threadIdx.x) >> 5;
    int lane = threadIdx.x & 31;
    if (w >= ETOT) return;
    int s, d; edge_sd(ei, w, s, d);
    float alpha[HH];
#pragma unroll
    for (int h = 0; h < HH; h++)
        alpha[h] = g_e1[w * HH + h] / (g_sum1[d * HH + h] + 1e-16f);
    const float* hrow = &g_hfeat1[(size_t)s * HC];
    float* orow = &g_out1[(size_t)d * HC];
#pragma unroll
    for (int k = 0; k < 8; k++) {
        int c = k * 32 + lane;
        atomicAdd(&orow[c], hrow[c] * alpha[k >> 1]);
    }
}

// h1 = elu(out1 + b1) + res1, in place into g_out1
__global__ void finalize1(const float* __restrict__ b1) {
    int i = blockIdx.x * blockDim.x + threadIdx.x;
    int stride = gridDim.x * blockDim.x;
    for (int j = i; j < NN * HC; j += stride) {
        float v = g_out1[j] + b1[j & (HC - 1)];
        float e = (v > 0.f) ? v : (__expf(v) - 1.f);
        g_out1[j] = e + g_res1[j];
    }
}

// ---------------- layer-2 edge passes ----------------
__global__ void edge_a2(const int* __restrict__ ei) {
    int ee = blockIdx.x * blockDim.x + threadIdx.x;
    if (ee >= ETOT) return;
    int s, d; edge_sd(ei, ee, s, d);
    float e = g_asrc2[s] + g_adst2[d];
    e = (e > 0.f) ? e : NEG_SLOPE * e;
    g_e2[ee] = e;
    atomicMax(&g_max2[d], f2u(e));
}

__global__ void edge_b2(const int* __restrict__ ei) {
    int ee = blockIdx.x * blockDim.x + threadIdx.x;
    if (ee >= ETOT) return;
    int s, d; edge_sd(ei, ee, s, d);
    (void)s;
    float ex = __expf(g_e2[ee] - u2f(g_max2[d]));
    g_e2[ee] = ex;
    atomicAdd(&g_sum2[d], ex);
}

__global__ void edge_c2(const int* __restrict__ ei, float* __restrict__ out) {
    int w = (blockIdx.x * blockDim.x + threadIdx.x) >> 5;
    int lane = threadIdx.x & 31;
    if (w >= ETOT) return;
    int s, d; edge_sd(ei, w, s, d);
    float alpha = g_e2[w] / (g_sum2[d] + 1e-16f);
    if (lane == 0) out[OFF_ALPHA + w] = alpha;
    const float* hrow = &g_hfeat2[(size_t)s * CC];
    float* orow = &g_out2[(size_t)d * CC];
    atomicAdd(&orow[lane],      hrow[lane]      * alpha);
    atomicAdd(&orow[lane + 32], hrow[lane + 32] * alpha);
}

// h2 = normalize(out2 + b2 + res2); write h2, logits
__global__ void finalize2(const float* __restrict__ b2,
                          const float* __restrict__ wact,
                          const float* __restrict__ bact,
                          float* __restrict__ out) {
    int n = (blockIdx.x * blockDim.x + threadIdx.x) >> 5;
    int lane = threadIdx.x & 31;
    if (n >= NN) return;
    int i0 = n * CC + lane, i1 = i0 + 32;
    float v0 = g_out2[i0] + b2[lane]      + g_res2[i0];
    float v1 = g_out2[i1] + b2[lane + 32] + g_res2[i1];
    float ss = wsum(v0 * v0 + v1 * v1);
    float norm = fmaxf(sqrtf(ss), 1e-12f);
    float h0 = v0 / norm, h1 = v1 / norm;
    out[OFF_H2 + i0] = h0;
    out[OFF_H2 + i1] = h1;
    float dot = wsum(h0 * wact[lane] + h1 * wact[lane + 32]);
    if (lane == 0) out[OFF_LOGITS + n] = dot + bact[0];
}

// ---------------- argmax ----------------
__global__ void argmax_part(const float* __restrict__ out) {
    __shared__ float sv[256];
    __shared__ int   si[256];
    int t = threadIdx.x;
    int n = blockIdx.x * 256 + t;
    sv[t] = (n < NN) ? out[OFF_LOGITS + n] : -CUDART_INF_F;
    si[t] = n;
    __syncthreads();
    for (int s = 128; s > 0; s >>= 1) {
        if (t < s) {
            if (sv[t + s] > sv[t] || (sv[t + s] == sv[t] && si[t + s] < si[t])) {
                sv[t] = sv[t + s]; si[t] = si[t + s];
            }
        }
        __syncthreads();
    }
    if (t == 0) { g_pval[blockIdx.x] = sv[0]; g_pidx[blockIdx.x] = si[0]; }
}

__global__ void argmax_final(float* __restrict__ out) {
    __shared__ float sv[256];
    __shared__ int   si[256];
    int t = threadIdx.x;
    sv[t] = (t < NB_ARGMAX) ? g_pval[t] : -CUDART_INF_F;
    si[t] = (t < NB_ARGMAX) ? g_pidx[t] : 0x7fffffff;
    __syncthreads();
    for (int s = 128; s > 0; s >>= 1) {
        if (t < s) {
            if (sv[t + s] > sv[t] || (sv[t + s] == sv[t] && si[t + s] < si[t])) {
                sv[t] = sv[t + s]; si[t] = si[t + s];
            }
        }
        __syncthreads();
    }
    if (t == 0) out[OFF_ACTION] = (float)si[0];
}

// ---------------- launch ----------------
extern "C" void kernel_launch(void* const* d_in, const int* in_sizes, int n_in,
                              void* d_out, int out_size) {
    const float* x    = (const float*)d_in[0];
    const int*   ei   = (const int*)  d_in[1];
    const float* W1   = (const float*)d_in[2];
    const float* as1  = (const float*)d_in[3];
    const float* ad1  = (const float*)d_in[4];
    const float* b1   = (const float*)d_in[5];
    const float* W2   = (const float*)d_in[6];
    const float* as2  = (const float*)d_in[7];
    const float* ad2  = (const float*)d_in[8];
    const float* b2   = (const float*)d_in[9];
    const float* Wr1  = (const float*)d_in[10];
    const float* Wr2  = (const float*)d_in[11];
    const float* wact = (const float*)d_in[12];
    const float* bact = (const float*)d_in[13];
    float* out = (float*)d_out;

    void *p_hf1, *p_r1, *p_o1, *p_hf2, *p_r2;
    cudaGetSymbolAddress(&p_hf1, g_hfeat1);
    cudaGetSymbolAddress(&p_r1,  g_res1);
    cudaGetSymbolAddress(&p_o1,  g_out1);
    cudaGetSymbolAddress(&p_hf2, g_hfeat2);
    cudaGetSymbolAddress(&p_r2,  g_res2);

    init_kernel<<<1024, 256>>>();

    // layer 1
    sgemm<<<dim3(4, (NN + 63) / 64), 256>>>(x, W1,  (float*)p_hf1, NN, FF, HC);
    sgemm<<<dim3(4, (NN + 63) / 64), 256>>>(x, Wr1, (float*)p_r1,  NN, FF, HC);
    attn1_kernel<<<(NN * HH * 32 + 255) / 256, 256>>>(as1, ad1);
    edge_a1<<<(ETOT * HH + 255) / 256, 256>>>(ei);
    edge_b1<<<(ETOT * HH + 255) / 256, 256>>>(ei);
    edge_c1<<<(ETOT * 32 + 255) / 256, 256>>>(ei);
    finalize1<<<4096, 256>>>(b1);

    // layer 2
    sgemm<<<dim3(1, (NN + 63) / 64), 256>>>((const float*)p_o1, W2,  (float*)p_hf2, NN, HC, CC);
    sgemm<<<dim3(1, (NN + 63) / 64), 256>>>((const float*)p_o1, Wr2, (float*)p_r2,  NN, HC, CC);
    attn2_kernel<<<(NN * 32 + 255) / 256, 256>>>(as2, ad2);
    edge_a2<<<(ETOT + 255) / 256, 256>>>(ei);
    edge_b2<<<(ETOT + 255) / 256, 256>>>(ei);
    edge_c2<<<(ETOT * 32 + 255) / 256, 256>>>(ei, out);
    finalize2<<<(NN * 32 + 255) / 256, 256>>>(b2, wact, bact, out);

    argmax_part<<<NB_ARGMAX, 256>>>(out);
    argmax_final<<<1, 256>>>(out);
}

// round 2
// speedup vs baseline: 1.4022x; 1.4022x over previous
#include <cuda_runtime.h>
#include <cuda_bf16.h>
#include <math_constants.h>

// Problem constants (fixed by the dataset)
#define NN   50000
#define FF   128
#define HH   4
#define CC   64
#define EE   400000
#define ETOT (EE + NN)          // edges + self loops = 450000
#define HC   (HH * CC)          // 256
#define NEG_SLOPE 0.2f

// Output layout: [action(1), h2(N*C), alpha2(ETOT), logits(N)]
#define OFF_ACTION 0
#define OFF_H2     1
#define OFF_ALPHA  (1 + NN * CC)
#define OFF_LOGITS (1 + NN * CC + ETOT)

// ---------------- scratch (static device globals; no allocation) ----------------
__device__ float    g_hfeat1[NN * HC];   // x @ W1
__device__ float    g_res1  [NN * HC];   // x @ W_res1
__device__ float    g_out1  [NN * HC];   // layer-1 aggregate -> becomes h1
__device__ float    g_asrc1 [NN * HH];
__device__ float    g_adst1 [NN * HH];
__device__ float    g_e1    [ETOT * HH];
__device__ float    g_sum1  [NN * HH];
__device__ unsigned g_max1  [NN * HH];

__device__ float    g_hfeat2[NN * CC];   // h1 @ W2
__device__ float    g_res2  [NN * CC];   // h1 @ W_res2
__device__ float    g_out2  [NN * CC];
__device__ float    g_asrc2 [NN];
__device__ float    g_adst2 [NN];
__device__ float    g_e2    [ETOT];
__device__ float    g_sum2  [NN];
__device__ unsigned g_max2  [NN];

#define NB_ARGMAX 196
__device__ float g_pval[NB_ARGMAX];
__device__ int   g_pidx[NB_ARGMAX];

// ---------------- helpers ----------------
__device__ __forceinline__ float wsum(float v) {
#pragma unroll
    for (int o = 16; o; o >>= 1) v += __shfl_xor_sync(0xffffffffu, v, o);
    return v;
}
// order-preserving float <-> uint for atomicMax on signed floats
__device__ __forceinline__ unsigned f2u(float f) {
    unsigned u = __float_as_uint(f);
    return (u & 0x80000000u) ? ~u : (u | 0x80000000u);
}
__device__ __forceinline__ float u2f(unsigned u) {
    return __uint_as_float((u & 0x80000000u) ? (u & 0x7fffffffu) : ~u);
}
__device__ __forceinline__ unsigned cvt_tf32(float f) {
    unsigned r;
    asm("cvt.rna.tf32.f32 %0, %1;" : "=r"(r) : "f"(f));
    return r;
}
__device__ __forceinline__ void mma_tf32(float* c, const unsigned* a, unsigned b0, unsigned b1) {
    asm volatile(
        "mma.sync.aligned.m16n8k8.row.col.f32.tf32.tf32.f32 "
        "{%0,%1,%2,%3}, {%4,%5,%6,%7}, {%8,%9}, {%0,%1,%2,%3};"
        : "+f"(c[0]), "+f"(c[1]), "+f"(c[2]), "+f"(c[3])
        : "r"(a[0]), "r"(a[1]), "r"(a[2]), "r"(a[3]), "r"(b0), "r"(b1));
}

// ---------------- init ----------------
__global__ void init_kernel() {
    int i = blockIdx.x * blockDim.x + threadIdx.x;
    int stride = gridDim.x * blockDim.x;
    for (int j = i; j < NN * HC; j += stride) g_out1[j] = 0.f;
    for (int j = i; j < NN * CC; j += stride) g_out2[j] = 0.f;
    for (int j = i; j < NN * HH; j += stride) { g_sum1[j] = 0.f; g_max1[j] = 0u; }
    for (int j = i; j < NN;      j += stride) { g_sum2[j] = 0.f; g_max2[j] = 0u; }
}

// ---------------- TF32 tensor-core GEMM: C[M,N] = A[M,K] @ B[K,N] ----------------
// Block tile 128x64, BK=16, 256 threads (8 warps as 4x2), warp tile 32x32.
// A,B converted to tf32 (round-to-nearest) at SMEM store time. fp32 accumulate.
#define GBM 128
#define GBN 64
#define GBK 16
#define ASTRIDE (GBK + 4)   // 20 floats -> conflict-free frag loads
#define BSTRIDE (GBN + 8)   // 72 floats -> conflict-free frag loads

__global__ __launch_bounds__(256) void gemm_tf32(
    const float* __restrict__ A, const float* __restrict__ B,
    float* __restrict__ C, int M, int N, int K)
{
    __shared__ unsigned As[GBM][ASTRIDE];   // row-major [m][k]
    __shared__ unsigned Bs[GBK][BSTRIDE];   // [k][n]
    const int tid  = threadIdx.x;
    const int lane = tid & 31;
    const int warp = tid >> 5;
    const int wm   = warp & 3;     // 0..3  (32 rows each)
    const int wn   = warp >> 2;    // 0..1  (32 cols each)
    const int bm   = blockIdx.y * GBM;
    const int bn   = blockIdx.x * GBN;

    float acc[2][4][4];
#pragma unroll
    for (int mi = 0; mi < 2; mi++)
#pragma unroll
        for (int nj = 0; nj < 4; nj++)
#pragma unroll
            for (int q = 0; q < 4; q++) acc[mi][nj][q] = 0.f;

    const int ar  = tid >> 2;          // 0..63 (and +64)
    const int akc = (tid & 3) * 4;     // 0,4,8,12
    const int bk  = tid >> 4;          // 0..15
    const int bnc = (tid & 15) * 4;    // 0..60

    const bool a0ok = (bm + ar)      < M;
    const bool a1ok = (bm + ar + 64) < M;

    for (int k0 = 0; k0 < K; k0 += GBK) {
        float4 a0v = make_float4(0.f, 0.f, 0.f, 0.f);
        float4 a1v = a0v;
        if (a0ok) a0v = *(const float4*)&A[(size_t)(bm + ar)      * K + k0 + akc];
        if (a1ok) a1v = *(const float4*)&A[(size_t)(bm + ar + 64) * K + k0 + akc];
        float4 bv = *(const float4*)&B[(size_t)(k0 + bk) * N + bn + bnc];
        __syncthreads();
        As[ar][akc + 0] = cvt_tf32(a0v.x);
        As[ar][akc + 1] = cvt_tf32(a0v.y);
        As[ar][akc + 2] = cvt_tf32(a0v.z);
        As[ar][akc + 3] = cvt_tf32(a0v.w);
        As[ar + 64][akc + 0] = cvt_tf32(a1v.x);
        As[ar + 64][akc + 1] = cvt_tf32(a1v.y);
        As[ar + 64][akc + 2] = cvt_tf32(a1v.z);
        As[ar + 64][akc + 3] = cvt_tf32(a1v.w);
        Bs[bk][bnc + 0] = cvt_tf32(bv.x);
        Bs[bk][bnc + 1] = cvt_tf32(bv.y);
        Bs[bk][bnc + 2] = cvt_tf32(bv.z);
        Bs[bk][bnc + 3] = cvt_tf32(bv.w);
        __syncthreads();

#pragma unroll
        for (int ks = 0; ks < GBK; ks += 8) {
            unsigned af[2][4];
#pragma unroll
            for (int mi = 0; mi < 2; mi++) {
                int r = wm * 32 + mi * 16 + (lane >> 2);
                int kk = ks + (lane & 3);
                af[mi][0] = As[r][kk];
                af[mi][1] = As[r + 8][kk];
                af[mi][2] = As[r][kk + 4];
                af[mi][3] = As[r + 8][kk + 4];
            }
#pragma unroll
            for (int nj = 0; nj < 4; nj++) {
                int c = wn * 32 + nj * 8 + (lane >> 2);
                unsigned b0 = Bs[ks + (lane & 3)][c];
                unsigned b1 = Bs[ks + (lane & 3) + 4][c];
                mma_tf32(acc[0][nj], af[0], b0, b1);
                mma_tf32(acc[1][nj], af[1], b0, b1);
            }
        }
    }

#pragma unroll
    for (int mi = 0; mi < 2; mi++) {
#pragma unroll
        for (int nj = 0; nj < 4; nj++) {
            int r0 = bm + wm * 32 + mi * 16 + (lane >> 2);
            int cc = bn + wn * 32 + nj * 8 + (lane & 3) * 2;
            if (r0 < M)
                *(float2*)&C[(size_t)r0 * N + cc] = make_float2(acc[mi][nj][0], acc[mi][nj][1]);
            if (r0 + 8 < M)
                *(float2*)&C[(size_t)(r0 + 8) * N + cc] = make_float2(acc[mi][nj][2], acc[mi][nj][3]);
        }
    }
}

// ---------------- attention dot products ----------------
__global__ void attn1_kernel(const float* __restrict__ as, const float* __restrict__ ad) {
    int w = (blockIdx.x * blockDim.x + threadIdx.x) >> 5;
    int lane = threadIdx.x & 31;
    if (w >= NN * HH) return;
    int n = w >> 2, hh = w & 3;
    const float* hrow = &g_hfeat1[n * HC + hh * CC];
    float v0 = hrow[lane], v1 = hrow[lane + 32];
    float ps = v0 * as[hh * CC + lane] + v1 * as[hh * CC + lane + 32];
    float pd = v0 * ad[hh * CC + lane] + v1 * ad[hh * CC + lane + 32];
    ps = wsum(ps);
    pd = wsum(pd);
    if (lane == 0) { g_asrc1[w] = ps; g_adst1[w] = pd; }
}

__global__ void attn2_kernel(const float* __restrict__ as, const float* __restrict__ ad) {
    int n = (blockIdx.x * blockDim.x + threadIdx.x) >> 5;
    int lane = threadIdx.x & 31;
    if (n >= NN) return;
    const float* hrow = &g_hfeat2[n * CC];
    float v0 = hrow[lane], v1 = hrow[lane + 32];
    float ps = v0 * as[lane] + v1 * as[lane + 32];
    float pd = v0 * ad[lane] + v1 * ad[lane + 32];
    ps = wsum(ps);
    pd = wsum(pd);
    if (lane == 0) { g_asrc2[n] = ps; g_adst2[n] = pd; }
}

// ---------------- edge passes ----------------
__device__ __forceinline__ void edge_sd(const int* __restrict__ ei, int ee, int& s, int& d) {
    if (ee < EE) { s = ei[ee]; d = ei[EE + ee]; }
    else         { s = d = ee - EE; }
}

__global__ void edge_a1(const int* __restrict__ ei) {
    int idx = blockIdx.x * blockDim.x + threadIdx.x;
    if (idx >= ETOT * HH) return;
    int ee = idx >> 2, hh = idx & 3;
    int s, d; edge_sd(ei, ee, s, d);
    float e = g_asrc1[s * HH + hh] + g_adst1[d * HH + hh];
    e = (e > 0.f) ? e : NEG_SLOPE * e;
    g_e1[idx] = e;
    atomicMax(&g_max1[d * HH + hh], f2u(e));
}

__global__ void edge_b1(const int* __restrict__ ei) {
    int idx = blockIdx.x * blockDim.x + threadIdx.x;
    if (idx >= ETOT * HH) return;
    int ee = idx >> 2, hh = idx & 3;
    int s, d; edge_sd(ei, ee, s, d);
    (void)s;
    float ex = __expf(g_e1[idx] - u2f(g_max1[d * HH + hh]));
    g_e1[idx] = ex;
    atomicAdd(&g_sum1[d * HH + hh], ex);
}

__global__ void edge_c1(const int* __restrict__ ei) {
    int w = (blockIdx.x * blockDim.x + threadIdx.x) >> 5;
    int lane = threadIdx.x & 31;
    if (w >= ETOT) return;
    int s, d; edge_sd(ei, w, s, d);
    float alpha[HH];
#pragma unroll
    for (int h = 0; h < HH; h++)
        alpha[h] = g_e1[w * HH + h] / (g_sum1[d * HH + h] + 1e-16f);
    const float* hrow = &g_hfeat1[(size_t)s * HC];
    float* orow = &g_out1[(size_t)d * HC];
#pragma unroll
    for (int k = 0; k < 8; k++) {
        int c = k * 32 + lane;
        atomicAdd(&orow[c], hrow[c] * alpha[k >> 1]);
    }
}

__global__ void finalize1(const float* __restrict__ b1) {
    int i = blockIdx.x * blockDim.x + threadIdx.x;
    int stride = gridDim.x * blockDim.x;
    for (int j = i; j < NN * HC; j += stride) {
        float v = g_out1[j] + b1[j & (HC - 1)];
        float e = (v > 0.f) ? v : (__expf(v) - 1.f);
        g_out1[j] = e + g_res1[j];
    }
}

__global__ void edge_a2(const int* __restrict__ ei) {
    int ee = blockIdx.x * blockDim.x + threadIdx.x;
    if (ee >= ETOT) return;
    int s, d; edge_sd(ei, ee, s, d);
    float e = g_asrc2[s] + g_adst2[d];
    e = (e > 0.f) ? e : NEG_SLOPE * e;
    g_e2[ee] = e;
    atomicMax(&g_max2[d], f2u(e));
}

__global__ void edge_b2(const int* __restrict__ ei) {
    int ee = blockIdx.x * blockDim.x + threadIdx.x;
    if (ee >= ETOT) return;
    int s, d; edge_sd(ei, ee, s, d);
    (void)s;
    float ex = __expf(g_e2[ee] - u2f(g_max2[d]));
    g_e2[ee] = ex;
    atomicAdd(&g_sum2[d], ex);
}

__global__ void edge_c2(const int* __restrict__ ei, float* __restrict__ out) {
    int w = (blockIdx.x * blockDim.x + threadIdx.x) >> 5;
    int lane = threadIdx.x & 31;
    if (w >= ETOT) return;
    int s, d; edge_sd(ei, w, s, d);
    float alpha = g_e2[w] / (g_sum2[d] + 1e-16f);
    if (lane == 0) out[OFF_ALPHA + w] = alpha;
    const float* hrow = &g_hfeat2[(size_t)s * CC];
    float* orow = &g_out2[(size_t)d * CC];
    atomicAdd(&orow[lane],      hrow[lane]      * alpha);
    atomicAdd(&orow[lane + 32], hrow[lane + 32] * alpha);
}

__global__ void finalize2(const float* __restrict__ b2,
                          const float* __restrict__ wact,
                          const float* __restrict__ bact,
                          float* __restrict__ out) {
    int n = (blockIdx.x * blockDim.x + threadIdx.x) >> 5;
    int lane = threadIdx.x & 31;
    if (n >= NN) return;
    int i0 = n * CC + lane, i1 = i0 + 32;
    float v0 = g_out2[i0] + b2[lane]      + g_res2[i0];
    float v1 = g_out2[i1] + b2[lane + 32] + g_res2[i1];
    float ss = wsum(v0 * v0 + v1 * v1);
    float norm = fmaxf(sqrtf(ss), 1e-12f);
    float h0 = v0 / norm, h1 = v1 / norm;
    out[OFF_H2 + i0] = h0;
    out[OFF_H2 + i1] = h1;
    float dot = wsum(h0 * wact[lane] + h1 * wact[lane + 32]);
    if (lane == 0) out[OFF_LOGITS + n] = dot + bact[0];
}

// ---------------- argmax ----------------
__global__ void argmax_part(const float* __restrict__ out) {
    __shared__ float sv[256];
    __shared__ int   si[256];
    int t = threadIdx.x;
    int n = blockIdx.x * 256 + t;
    sv[t] = (n < NN) ? out[OFF_LOGITS + n] : -CUDART_INF_F;
    si[t] = n;
    __syncthreads();
    for (int s = 128; s > 0; s >>= 1) {
        if (t < s) {
            if (sv[t + s] > sv[t] || (sv[t + s] == sv[t] && si[t + s] < si[t])) {
                sv[t] = sv[t + s]; si[t] = si[t + s];
            }
        }
        __syncthreads();
    }
    if (t == 0) { g_pval[blockIdx.x] = sv[0]; g_pidx[blockIdx.x] = si[0]; }
}

__global__ void argmax_final(float* __restrict__ out) {
    __shared__ float sv[256];
    __shared__ int   si[256];
    int t = threadIdx.x;
    sv[t] = (t < NB_ARGMAX) ? g_pval[t] : -CUDART_INF_F;
    si[t] = (t < NB_ARGMAX) ? g_pidx[t] : 0x7fffffff;
    __syncthreads();
    for (int s = 128; s > 0; s >>= 1) {
        if (t < s) {
            if (sv[t + s] > sv[t] || (sv[t + s] == sv[t] && si[t + s] < si[t])) {
                sv[t] = sv[t + s]; si[t] = si[t + s];
            }
        }
        __syncthreads();
    }
    if (t == 0) out[OFF_ACTION] = (float)si[0];
}

// ---------------- launch ----------------
extern "C" void kernel_launch(void* const* d_in, const int* in_sizes, int n_in,
                              void* d_out, int out_size) {
    const float* x    = (const float*)d_in[0];
    const int*   ei   = (const int*)  d_in[1];
    const float* W1   = (const float*)d_in[2];
    const float* as1  = (const float*)d_in[3];
    const float* ad1  = (const float*)d_in[4];
    const float* b1   = (const float*)d_in[5];
    const float* W2   = (const float*)d_in[6];
    const float* as2  = (const float*)d_in[7];
    const float* ad2  = (const float*)d_in[8];
    const float* b2   = (const float*)d_in[9];
    const float* Wr1  = (const float*)d_in[10];
    const float* Wr2  = (const float*)d_in[11];
    const float* wact = (const float*)d_in[12];
    const float* bact = (const float*)d_in[13];
    float* out = (float*)d_out;

    void *p_hf1, *p_r1, *p_o1, *p_hf2, *p_r2;
    cudaGetSymbolAddress(&p_hf1, g_hfeat1);
    cudaGetSymbolAddress(&p_r1,  g_res1);
    cudaGetSymbolAddress(&p_o1,  g_out1);
    cudaGetSymbolAddress(&p_hf2, g_hfeat2);
    cudaGetSymbolAddress(&p_r2,  g_res2);

    init_kernel<<<1024, 256>>>();

    const int MB = (NN + GBM - 1) / GBM;   // 391

    // layer 1: [50000,128] @ [128,256] twice
    gemm_tf32<<<dim3(HC / GBN, MB), 256>>>(x, W1,  (float*)p_hf1, NN, HC, FF);
    gemm_tf32<<<dim3(HC / GBN, MB), 256>>>(x, Wr1, (float*)p_r1,  NN, HC, FF);
    attn1_kernel<<<(NN * HH * 32 + 255) / 256, 256>>>(as1, ad1);
    edge_a1<<<(ETOT * HH + 255) / 256, 256>>>(ei);
    edge_b1<<<(ETOT * HH + 255) / 256, 256>>>(ei);
    edge_c1<<<(ETOT * 32 + 255) / 256, 256>>>(ei);
    finalize1<<<4096, 256>>>(b1);

    // layer 2: [50000,256] @ [256,64] twice
    gemm_tf32<<<dim3(CC / GBN, MB), 256>>>((const float*)p_o1, W2,  (float*)p_hf2, NN, CC, HC);
    gemm_tf32<<<dim3(CC / GBN, MB), 256>>>((const float*)p_o1, Wr2, (float*)p_r2,  NN, CC, HC);
    attn2_kernel<<<(NN * 32 + 255) / 256, 256>>>(as2, ad2);
    edge_a2<<<(ETOT + 255) / 256, 256>>>(ei);
    edge_b2<<<(ETOT + 255) / 256, 256>>>(ei);
    edge_c2<<<(ETOT * 32 + 255) / 256, 256>>>(ei, out);
    finalize2<<<(NN * 32 + 255) / 256, 256>>>(b2, wact, bact, out);

    argmax_part<<<NB_ARGMAX, 256>>>(out);
    argmax_final<<<1, 256>>>(out);
}

// round 3
// speedup vs baseline: 1.8262x; 1.3024x over previous
#include <cuda_runtime.h>
#include <cuda_bf16.h>
#include <math_constants.h>

// Problem constants (fixed by the dataset)
#define NN   50000
#define FF   128
#define HH   4
#define CC   64
#define EE   400000
#define ETOT (EE + NN)          // edges + self loops = 450000
#define HC   (HH * CC)          // 256
#define NEG_SLOPE 0.2f

// Output layout: [action(1), h2(N*C), alpha2(ETOT), logits(N)]
#define OFF_ACTION 0
#define OFF_H2     1
#define OFF_ALPHA  (1 + NN * CC)
#define OFF_LOGITS (1 + NN * CC + ETOT)

// ---------------- scratch (static device globals; no allocation) ----------------
__device__ float g_hfeat1[NN * HC];   // x @ W1
__device__ float g_res1  [NN * HC];   // x @ W_res1
__device__ float g_out1  [NN * HC];   // h1 after gather+elu+residual
__device__ float g_asrc1 [NN * HH];
__device__ float g_adst1 [NN * HH];

__device__ float g_hfeat2[NN * CC];   // h1 @ W2
__device__ float g_res2  [NN * CC];   // h1 @ W_res2
__device__ float g_asrc2 [NN];
__device__ float g_adst2 [NN];

// CSR (destination-sorted adjacency, shared by both layers)
__device__ int g_deg   [NN];
__device__ int g_cur   [NN];
__device__ int g_rowptr[NN + 1];
__device__ int g_esrc  [ETOT];
__device__ int g_eid   [ETOT];

#define NB_ARGMAX 196
__device__ float g_pval[NB_ARGMAX];
__device__ int   g_pidx[NB_ARGMAX];

// ---------------- helpers ----------------
__device__ __forceinline__ float wsum(float v) {
#pragma unroll
    for (int o = 16; o; o >>= 1) v += __shfl_xor_sync(0xffffffffu, v, o);
    return v;
}
__device__ __forceinline__ float wmax(float v) {
#pragma unroll
    for (int o = 16; o; o >>= 1) v = fmaxf(v, __shfl_xor_sync(0xffffffffu, v, o));
    return v;
}
__device__ __forceinline__ float lrelu(float e) {
    return (e > 0.f) ? e : NEG_SLOPE * e;
}
__device__ __forceinline__ unsigned cvt_tf32(float f) {
    unsigned r;
    asm("cvt.rna.tf32.f32 %0, %1;" : "=r"(r) : "f"(f));
    return r;
}
__device__ __forceinline__ void mma_tf32(float* c, const unsigned* a, unsigned b0, unsigned b1) {
    asm volatile(
        "mma.sync.aligned.m16n8k8.row.col.f32.tf32.tf32.f32 "
        "{%0,%1,%2,%3}, {%4,%5,%6,%7}, {%8,%9}, {%0,%1,%2,%3};"
        : "+f"(c[0]), "+f"(c[1]), "+f"(c[2]), "+f"(c[3])
        : "r"(a[0]), "r"(a[1]), "r"(a[2]), "r"(a[3]), "r"(b0), "r"(b1));
}

// dst of concatenated edge list (edges then self-loops)
__device__ __forceinline__ void edge_sd(const int* __restrict__ ei, int ee, int& s, int& d) {
    if (ee < EE) { s = ei[ee]; d = ei[EE + ee]; }
    else         { s = d = ee - EE; }
}

// ---------------- CSR build ----------------
__global__ void init_kernel() {
    int i = blockIdx.x * blockDim.x + threadIdx.x;
    if (i < NN) { g_deg[i] = 0; g_cur[i] = 0; }
}

__global__ void csr_count(const int* __restrict__ ei) {
    int ee = blockIdx.x * blockDim.x + threadIdx.x;
    if (ee >= ETOT) return;
    int d = (ee < EE) ? ei[EE + ee] : ee - EE;
    atomicAdd(&g_deg[d], 1);
}

// single-block exclusive scan of g_deg -> g_rowptr  (50001 entries)
__global__ __launch_bounds__(1024) void csr_scan() {
    __shared__ int sp[1024];
    const int t = threadIdx.x;
    const int CH = (NN + 1023) / 1024;
    int b = t * CH, e_ = min(b + CH, NN);
    int s = 0;
    for (int i = b; i < e_; i++) s += g_deg[i];
    sp[t] = s;
    __syncthreads();
    for (int off = 1; off < 1024; off <<= 1) {
        int v = (t >= off) ? sp[t - off] : 0;
        __syncthreads();
        sp[t] += v;
        __syncthreads();
    }
    int run = sp[t] - s;    // exclusive prefix
    for (int i = b; i < e_; i++) { g_rowptr[i] = run; run += g_deg[i]; }
    if (t == 1023) g_rowptr[NN] = sp[1023];
}

__global__ void csr_scatter(const int* __restrict__ ei) {
    int ee = blockIdx.x * blockDim.x + threadIdx.x;
    if (ee >= ETOT) return;
    int s, d; edge_sd(ei, ee, s, d);
    int pos = g_rowptr[d] + atomicAdd(&g_cur[d], 1);
    g_esrc[pos] = s;
    g_eid[pos]  = ee;
}

// ---------------- TF32 tensor-core GEMM: C[M,N] = A[M,K] @ B[K,N] ----------------
#define GBM 128
#define GBN 64
#define GBK 16
#define ASTRIDE (GBK + 4)
#define BSTRIDE (GBN + 8)

__global__ __launch_bounds__(256) void gemm_tf32(
    const float* __restrict__ A, const float* __restrict__ B,
    float* __restrict__ C, int M, int N, int K)
{
    __shared__ unsigned As[GBM][ASTRIDE];
    __shared__ unsigned Bs[GBK][BSTRIDE];
    const int tid  = threadIdx.x;
    const int lane = tid & 31;
    const int warp = tid >> 5;
    const int wm   = warp & 3;
    const int wn   = warp >> 2;
    const int bm   = blockIdx.y * GBM;
    const int bn   = blockIdx.x * GBN;

    float acc[2][4][4];
#pragma unroll
    for (int mi = 0; mi < 2; mi++)
#pragma unroll
        for (int nj = 0; nj < 4; nj++)
#pragma unroll
            for (int q = 0; q < 4; q++) acc[mi][nj][q] = 0.f;

    const int ar  = tid >> 2;
    const int akc = (tid & 3) * 4;
    const int bk  = tid >> 4;
    const int bnc = (tid & 15) * 4;
    const bool a0ok = (bm + ar)      < M;
    const bool a1ok = (bm + ar + 64) < M;

    for (int k0 = 0; k0 < K; k0 += GBK) {
        float4 a0v = make_float4(0.f, 0.f, 0.f, 0.f);
        float4 a1v = a0v;
        if (a0ok) a0v = *(const float4*)&A[(size_t)(bm + ar)      * K + k0 + akc];
        if (a1ok) a1v = *(const float4*)&A[(size_t)(bm + ar + 64) * K + k0 + akc];
        float4 bv = *(const float4*)&B[(size_t)(k0 + bk) * N + bn + bnc];
        __syncthreads();
        As[ar][akc + 0] = cvt_tf32(a0v.x);
        As[ar][akc + 1] = cvt_tf32(a0v.y);
        As[ar][akc + 2] = cvt_tf32(a0v.z);
        As[ar][akc + 3] = cvt_tf32(a0v.w);
        As[ar + 64][akc + 0] = cvt_tf32(a1v.x);
        As[ar + 64][akc + 1] = cvt_tf32(a1v.y);
        As[ar + 64][akc + 2] = cvt_tf32(a1v.z);
        As[ar + 64][akc + 3] = cvt_tf32(a1v.w);
        Bs[bk][bnc + 0] = cvt_tf32(bv.x);
        Bs[bk][bnc + 1] = cvt_tf32(bv.y);
        Bs[bk][bnc + 2] = cvt_tf32(bv.z);
        Bs[bk][bnc + 3] = cvt_tf32(bv.w);
        __syncthreads();

#pragma unroll
        for (int ks = 0; ks < GBK; ks += 8) {
            unsigned af[2][4];
#pragma unroll
            for (int mi = 0; mi < 2; mi++) {
                int r = wm * 32 + mi * 16 + (lane >> 2);
                int kk = ks + (lane & 3);
                af[mi][0] = As[r][kk];
                af[mi][1] = As[r + 8][kk];
                af[mi][2] = As[r][kk + 4];
                af[mi][3] = As[r + 8][kk + 4];
            }
#pragma unroll
            for (int nj = 0; nj < 4; nj++) {
                int c = wn * 32 + nj * 8 + (lane >> 2);
                unsigned b0 = Bs[ks + (lane & 3)][c];
                unsigned b1 = Bs[ks + (lane & 3) + 4][c];
                mma_tf32(acc[0][nj], af[0], b0, b1);
                mma_tf32(acc[1][nj], af[1], b0, b1);
            }
        }
    }

#pragma unroll
    for (int mi = 0; mi < 2; mi++) {
#pragma unroll
        for (int nj = 0; nj < 4; nj++) {
            int r0 = bm + wm * 32 + mi * 16 + (lane >> 2);
            int cc = bn + wn * 32 + nj * 8 + (lane & 3) * 2;
            if (r0 < M)
                *(float2*)&C[(size_t)r0 * N + cc] = make_float2(acc[mi][nj][0], acc[mi][nj][1]);
            if (r0 + 8 < M)
                *(float2*)&C[(size_t)(r0 + 8) * N + cc] = make_float2(acc[mi][nj][2], acc[mi][nj][3]);
        }
    }
}

// ---------------- attention dot products ----------------
__global__ void attn1_kernel(const float* __restrict__ as, const float* __restrict__ ad) {
    int w = (blockIdx.x * blockDim.x + threadIdx.x) >> 5;
    int lane = threadIdx.x & 31;
    if (w >= NN * HH) return;
    int n = w >> 2, hh = w & 3;
    const float* hrow = &g_hfeat1[n * HC + hh * CC];
    float v0 = hrow[lane], v1 = hrow[lane + 32];
    float ps = v0 * as[hh * CC + lane] + v1 * as[hh * CC + lane + 32];
    float pd = v0 * ad[hh * CC + lane] + v1 * ad[hh * CC + lane + 32];
    ps = wsum(ps);
    pd = wsum(pd);
    if (lane == 0) { g_asrc1[w] = ps; g_adst1[w] = pd; }
}

__global__ void attn2_kernel(const float* __restrict__ as, const float* __restrict__ ad) {
    int n = (blockIdx.x * blockDim.x + threadIdx.x) >> 5;
    int lane = threadIdx.x & 31;
    if (n >= NN) return;
    const float* hrow = &g_hfeat2[n * CC];
    float v0 = hrow[lane], v1 = hrow[lane + 32];
    float ps = v0 * as[lane] + v1 * as[lane + 32];
    float pd = v0 * ad[lane] + v1 * ad[lane + 32];
    ps = wsum(ps);
    pd = wsum(pd);
    if (lane == 0) { g_asrc2[n] = ps; g_adst2[n] = pd; }
}

// ---------------- layer-1 fused gather: softmax + aggregate + bias + elu + residual ----------------
__global__ __launch_bounds__(256) void gat1_gather(const float* __restrict__ b1) {
    int d = (blockIdx.x * blockDim.x + threadIdx.x) >> 5;
    int lane = threadIdx.x & 31;
    if (d >= NN) return;
    const int beg = g_rowptr[d], end = g_rowptr[d + 1];

    const float ad0 = g_adst1[d * HH + 0];
    const float ad1 = g_adst1[d * HH + 1];
    const float ad2 = g_adst1[d * HH + 2];
    const float ad3 = g_adst1[d * HH + 3];

    // pass A: per-head max (lanes edge-parallel)
    float m0 = -CUDART_INF_F, m1 = m0, m2 = m0, m3 = m0;
    for (int i = beg + lane; i < end; i += 32) {
        int s = g_esrc[i];
        m0 = fmaxf(m0, lrelu(g_asrc1[s * HH + 0] + ad0));
        m1 = fmaxf(m1, lrelu(g_asrc1[s * HH + 1] + ad1));
        m2 = fmaxf(m2, lrelu(g_asrc1[s * HH + 2] + ad2));
        m3 = fmaxf(m3, lrelu(g_asrc1[s * HH + 3] + ad3));
    }
    m0 = wmax(m0); m1 = wmax(m1); m2 = wmax(m2); m3 = wmax(m3);

    // pass B: per-head exp sum
    float s0 = 0.f, s1 = 0.f, s2 = 0.f, s3 = 0.f;
    for (int i = beg + lane; i < end; i += 32) {
        int s = g_esrc[i];
        s0 += __expf(lrelu(g_asrc1[s * HH + 0] + ad0) - m0);
        s1 += __expf(lrelu(g_asrc1[s * HH + 1] + ad1) - m1);
        s2 += __expf(lrelu(g_asrc1[s * HH + 2] + ad2) - m2);
        s3 += __expf(lrelu(g_asrc1[s * HH + 3] + ad3) - m3);
    }
    s0 = wsum(s0); s1 = wsum(s1); s2 = wsum(s2); s3 = wsum(s3);
    const float inv0 = 1.f / (s0 + 1e-16f);
    const float inv1 = 1.f / (s1 + 1e-16f);
    const float inv2 = 1.f / (s2 + 1e-16f);
    const float inv3 = 1.f / (s3 + 1e-16f);

    // pass C: aggregate (lanes channel-parallel, edges sequential)
    float acc[8] = {0.f, 0.f, 0.f, 0.f, 0.f, 0.f, 0.f, 0.f};
    for (int i = beg; i < end; i++) {
        int s = g_esrc[i];   // broadcast
        float a0 = __expf(lrelu(g_asrc1[s * HH + 0] + ad0) - m0) * inv0;
        float a1 = __expf(lrelu(g_asrc1[s * HH + 1] + ad1) - m1) * inv1;
        float a2 = __expf(lrelu(g_asrc1[s * HH + 2] + ad2) - m2) * inv2;
        float a3 = __expf(lrelu(g_asrc1[s * HH + 3] + ad3) - m3) * inv3;
        const float* hrow = &g_hfeat1[(size_t)s * HC];
        acc[0] += hrow[lane +   0] * a0;
        acc[1] += hrow[lane +  32] * a0;
        acc[2] += hrow[lane +  64] * a1;
        acc[3] += hrow[lane +  96] * a1;
        acc[4] += hrow[lane + 128] * a2;
        acc[5] += hrow[lane + 160] * a2;
        acc[6] += hrow[lane + 192] * a3;
        acc[7] += hrow[lane + 224] * a3;
    }

    // fused epilogue: +b1 -> elu -> +res1
    const size_t base = (size_t)d * HC;
#pragma unroll
    for (int k = 0; k < 8; k++) {
        int c = k * 32 + lane;
        float v = acc[k] + b1[c];
        v = (v > 0.f) ? v : (__expf(v) - 1.f);
        g_out1[base + c] = v + g_res1[base + c];
    }
}

// ---------------- layer-2 fused gather: softmax + aggregate + bias + residual + normalize + logits ----------------
__global__ __launch_bounds__(256) void gat2_gather(
    const float* __restrict__ b2, const float* __restrict__ wact,
    const float* __restrict__ bact, float* __restrict__ out)
{
    int d = (blockIdx.x * blockDim.x + threadIdx.x) >> 5;
    int lane = threadIdx.x & 31;
    if (d >= NN) return;
    const int beg = g_rowptr[d], end = g_rowptr[d + 1];
    const float add = g_adst2[d];

    float m = -CUDART_INF_F;
    for (int i = beg + lane; i < end; i += 32)
        m = fmaxf(m, lrelu(g_asrc2[g_esrc[i]] + add));
    m = wmax(m);

    float ssum = 0.f;
    for (int i = beg + lane; i < end; i += 32)
        ssum += __expf(lrelu(g_asrc2[g_esrc[i]] + add) - m);
    ssum = wsum(ssum);
    const float inv = 1.f / (ssum + 1e-16f);

    float acc0 = 0.f, acc1 = 0.f;
    for (int i = beg; i < end; i++) {
        int s = g_esrc[i];
        float alpha = __expf(lrelu(g_asrc2[s] + add) - m) * inv;
        if (lane == 0) out[OFF_ALPHA + g_eid[i]] = alpha;
        const float* hrow = &g_hfeat2[(size_t)s * CC];
        acc0 += hrow[lane]      * alpha;
        acc1 += hrow[lane + 32] * alpha;
    }

    const size_t base = (size_t)d * CC;
    float v0 = acc0 + b2[lane]      + g_res2[base + lane];
    float v1 = acc1 + b2[lane + 32] + g_res2[base + lane + 32];
    float ss = wsum(v0 * v0 + v1 * v1);
    float norm = fmaxf(sqrtf(ss), 1e-12f);
    float h0 = v0 / norm, h1 = v1 / norm;
    out[OFF_H2 + base + lane]      = h0;
    out[OFF_H2 + base + lane + 32] = h1;
    float dot = wsum(h0 * wact[lane] + h1 * wact[lane + 32]);
    if (lane == 0) out[OFF_LOGITS + d] = dot + bact[0];
}

// ---------------- argmax ----------------
__global__ void argmax_part(const float* __restrict__ out) {
    __shared__ float sv[256];
    __shared__ int   si[256];
    int t = threadIdx.x;
    int n = blockIdx.x * 256 + t;
    sv[t] = (n < NN) ? out[OFF_LOGITS + n] : -CUDART_INF_F;
    si[t] = n;
    __syncthreads();
    for (int s = 128; s > 0; s >>= 1) {
        if (t < s) {
            if (sv[t + s] > sv[t] || (sv[t + s] == sv[t] && si[t + s] < si[t])) {
                sv[t] = sv[t + s]; si[t] = si[t + s];
            }
        }
        __syncthreads();
    }
    if (t == 0) { g_pval[blockIdx.x] = sv[0]; g_pidx[blockIdx.x] = si[0]; }
}

__global__ void argmax_final(float* __restrict__ out) {
    __shared__ float sv[256];
    __shared__ int   si[256];
    int t = threadIdx.x;
    sv[t] = (t < NB_ARGMAX) ? g_pval[t] : -CUDART_INF_F;
    si[t] = (t < NB_ARGMAX) ? g_pidx[t] : 0x7fffffff;
    __syncthreads();
    for (int s = 128; s > 0; s >>= 1) {
        if (t < s) {
            if (sv[t + s] > sv[t] || (sv[t + s] == sv[t] && si[t + s] < si[t])) {
                sv[t] = sv[t + s]; si[t] = si[t + s];
            }
        }
        __syncthreads();
    }
    if (t == 0) out[OFF_ACTION] = (float)si[0];
}

// ---------------- launch ----------------
extern "C" void kernel_launch(void* const* d_in, const int* in_sizes, int n_in,
                              void* d_out, int out_size) {
    const float* x    = (const float*)d_in[0];
    const int*   ei   = (const int*)  d_in[1];
    const float* W1   = (const float*)d_in[2];
    const float* as1  = (const float*)d_in[3];
    const float* ad1  = (const float*)d_in[4];
    const float* b1   = (const float*)d_in[5];
    const float* W2   = (const float*)d_in[6];
    const float* as2  = (const float*)d_in[7];
    const float* ad2  = (const float*)d_in[8];
    const float* b2   = (const float*)d_in[9];
    const float* Wr1  = (const float*)d_in[10];
    const float* Wr2  = (const float*)d_in[11];
    const float* wact = (const float*)d_in[12];
    const float* bact = (const float*)d_in[13];
    float* out = (float*)d_out;

    void *p_hf1, *p_r1, *p_o1, *p_hf2, *p_r2;
    cudaGetSymbolAddress(&p_hf1, g_hfeat1);
    cudaGetSymbolAddress(&p_r1,  g_res1);
    cudaGetSymbolAddress(&p_o1,  g_out1);
    cudaGetSymbolAddress(&p_hf2, g_hfeat2);
    cudaGetSymbolAddress(&p_r2,  g_res2);

    // CSR build (shared by both layers)
    init_kernel<<<(NN + 255) / 256, 256>>>();
    csr_count<<<(ETOT + 255) / 256, 256>>>(ei);
    csr_scan<<<1, 1024>>>();
    csr_scatter<<<(ETOT + 255) / 256, 256>>>(ei);

    const int MB = (NN + GBM - 1) / GBM;

    // layer 1
    gemm_tf32<<<dim3(HC / GBN, MB), 256>>>(x, W1,  (float*)p_hf1, NN, HC, FF);
    gemm_tf32<<<dim3(HC / GBN, MB), 256>>>(x, Wr1, (float*)p_r1,  NN, HC, FF);
    attn1_kernel<<<(NN * HH * 32 + 255) / 256, 256>>>(as1, ad1);
    gat1_gather<<<(NN * 32 + 255) / 256, 256>>>(b1);

    // layer 2
    gemm_tf32<<<dim3(CC / GBN, MB), 256>>>((const float*)p_o1, W2,  (float*)p_hf2, NN, CC, HC);
    gemm_tf32<<<dim3(CC / GBN, MB), 256>>>((const float*)p_o1, Wr2, (float*)p_r2,  NN, CC, HC);
    attn2_kernel<<<(NN * 32 + 255) / 256, 256>>>(as2, ad2);
    gat2_gather<<<(NN * 32 + 255) / 256, 256>>>(b2, wact, bact, out);

    argmax_part<<<NB_ARGMAX, 256>>>(out);
    argmax_final<<<1, 256>>>(out);
}

// round 5
// speedup vs baseline: 1.8987x; 1.0397x over previous
#include <cuda_runtime.h>
#include <cuda_bf16.h>
#include <math_constants.h>

// Problem constants (fixed by the dataset)
#define NN   50000
#define FF   128
#define HH   4
#define CC   64
#define EE   400000
#define ETOT (EE + NN)          // edges + self loops = 450000
#define HC   (HH * CC)          // 256
#define NEG_SLOPE 0.2f

// Output layout: [action(1), h2(N*C), alpha2(ETOT), logits(N)]
#define OFF_ACTION 0
#define OFF_H2     1
#define OFF_ALPHA  (1 + NN * CC)
#define OFF_LOGITS (1 + NN * CC + ETOT)

// ---------------- scratch (static device globals; no allocation) ----------------
__device__ float g_hfeat1[NN * HC];   // x @ W1
__device__ float g_res1  [NN * HC];   // x @ W_res1
__device__ float g_out1  [NN * HC];   // h1 after gather+elu+residual
__device__ float g_asrc1 [NN * HH];
__device__ float g_adst1 [NN * HH];

__device__ float g_hfeat2[NN * CC];   // h1 @ W2
__device__ float g_res2  [NN * CC];   // h1 @ W_res2
__device__ float g_asrc2 [NN];
__device__ float g_adst2 [NN];

// CSR (destination-sorted adjacency, shared by both layers)
__device__ int g_deg   [NN];
__device__ int g_cur   [NN];
__device__ int g_rowptr[NN + 1];
__device__ int g_esrc  [ETOT];
__device__ int g_eid   [ETOT];

#define NB_ARGMAX 196
__device__ float g_pval[NB_ARGMAX];
__device__ int   g_pidx[NB_ARGMAX];

// ---------------- helpers ----------------
__device__ __forceinline__ float wsum(float v) {
#pragma unroll
    for (int o = 16; o; o >>= 1) v += __shfl_xor_sync(0xffffffffu, v, o);
    return v;
}
__device__ __forceinline__ float wmax(float v) {
#pragma unroll
    for (int o = 16; o; o >>= 1) v = fmaxf(v, __shfl_xor_sync(0xffffffffu, v, o));
    return v;
}
__device__ __forceinline__ float lrelu(float e) {
    return (e > 0.f) ? e : NEG_SLOPE * e;
}
__device__ __forceinline__ unsigned cvt_tf32(float f) {
    unsigned r;
    asm("cvt.rna.tf32.f32 %0, %1;" : "=r"(r) : "f"(f));
    return r;
}
__device__ __forceinline__ void mma_tf32(float* c, const unsigned* a, unsigned b0, unsigned b1) {
    asm volatile(
        "mma.sync.aligned.m16n8k8.row.col.f32.tf32.tf32.f32 "
        "{%0,%1,%2,%3}, {%4,%5,%6,%7}, {%8,%9}, {%0,%1,%2,%3};"
        : "+f"(c[0]), "+f"(c[1]), "+f"(c[2]), "+f"(c[3])
        : "r"(a[0]), "r"(a[1]), "r"(a[2]), "r"(a[3]), "r"(b0), "r"(b1));
}

// dst of concatenated edge list (edges then self-loops)
__device__ __forceinline__ void edge_sd(const int* __restrict__ ei, int ee, int& s, int& d) {
    if (ee < EE) { s = ei[ee]; d = ei[EE + ee]; }
    else         { s = d = ee - EE; }
}

// ---------------- CSR build ----------------
__global__ void init_kernel() {
    int i = blockIdx.x * blockDim.x + threadIdx.x;
    if (i < NN) { g_deg[i] = 0; g_cur[i] = 0; }
}

__global__ void csr_count(const int* __restrict__ ei) {
    int ee = blockIdx.x * blockDim.x + threadIdx.x;
    if (ee >= ETOT) return;
    int d = (ee < EE) ? ei[EE + ee] : ee - EE;
    atomicAdd(&g_deg[d], 1);
}

// single-block exclusive scan of g_deg -> g_rowptr  (50001 entries)
__global__ __launch_bounds__(1024) void csr_scan() {
    __shared__ int sp[1024];
    const int t = threadIdx.x;
    const int CH = (NN + 1023) / 1024;
    int b = t * CH, e_ = min(b + CH, NN);
    int s = 0;
    for (int i = b; i < e_; i++) s += g_deg[i];
    sp[t] = s;
    __syncthreads();
    for (int off = 1; off < 1024; off <<= 1) {
        int v = (t >= off) ? sp[t - off] : 0;
        __syncthreads();
        sp[t] += v;
        __syncthreads();
    }
    int run = sp[t] - s;    // exclusive prefix
    for (int i = b; i < e_; i++) { g_rowptr[i] = run; run += g_deg[i]; }
    if (t == 1023) g_rowptr[NN] = sp[1023];
}

__global__ void csr_scatter(const int* __restrict__ ei) {
    int ee = blockIdx.x * blockDim.x + threadIdx.x;
    if (ee >= ETOT) return;
    int s, d; edge_sd(ei, ee, s, d);
    int pos = g_rowptr[d] + atomicAdd(&g_cur[d], 1);
    g_esrc[pos] = s;
    g_eid[pos]  = ee;
}

// ---------------- TF32 GEMM, register-prefetch pipelined, optional fused attn dots ----------------
// C[M,N] = A[M,K] @ B[K,N]; if att_src != null also writes
//   asrc_out[r*astride + (bn+c)/CC] = sum_c C[r,c]*att_src[bn+c]  (block covers one CC-col group)
#define GBM 128
#define GBN 64
#define GBK 16
#define ASTRIDE (GBK + 4)
#define BSTRIDE (GBN + 8)

__global__ __launch_bounds__(256) void gemm_tf32(
    const float* __restrict__ A, const float* __restrict__ B,
    float* __restrict__ C, int M, int N, int K,
    const float* __restrict__ att_src, const float* __restrict__ att_dst,
    float* __restrict__ asrc_out, float* __restrict__ adst_out, int astride)
{
    __shared__ unsigned As[GBM][ASTRIDE];
    __shared__ unsigned Bs[GBK][BSTRIDE];
    __shared__ float sdot_s[GBM];
    __shared__ float sdot_d[GBM];
    const int tid  = threadIdx.x;
    const int lane = tid & 31;
    const int warp = tid >> 5;
    const int wm   = warp & 3;
    const int wn   = warp >> 2;
    const int bm   = blockIdx.y * GBM;
    const int bn   = blockIdx.x * GBN;

    float acc[2][4][4];
#pragma unroll
    for (int mi = 0; mi < 2; mi++)
#pragma unroll
        for (int nj = 0; nj < 4; nj++)
#pragma unroll
            for (int q = 0; q < 4; q++) acc[mi][nj][q] = 0.f;

    if (att_src && tid < GBM) { sdot_s[tid] = 0.f; sdot_d[tid] = 0.f; }

    const int ar  = tid >> 2;
    const int akc = (tid & 3) * 4;
    const int bk  = tid >> 4;
    const int bnc = (tid & 15) * 4;
    const bool a0ok = (bm + ar)      < M;
    const bool a1ok = (bm + ar + 64) < M;
    const float* Arow0 = &A[(size_t)(bm + ar)      * K + akc];
    const float* Arow1 = &A[(size_t)(bm + ar + 64) * K + akc];
    const float* Brow  = &B[(size_t)bk * N + bn + bnc];

    // prologue load
    float4 a0v = a0ok ? *(const float4*)&Arow0[0] : make_float4(0.f, 0.f, 0.f, 0.f);
    float4 a1v = a1ok ? *(const float4*)&Arow1[0] : make_float4(0.f, 0.f, 0.f, 0.f);
    float4 bv  = *(const float4*)&Brow[0];

    for (int k0 = 0; k0 < K; k0 += GBK) {
        __syncthreads();
        As[ar][akc + 0] = cvt_tf32(a0v.x);
        As[ar][akc + 1] = cvt_tf32(a0v.y);
        As[ar][akc + 2] = cvt_tf32(a0v.z);
        As[ar][akc + 3] = cvt_tf32(a0v.w);
        As[ar + 64][akc + 0] = cvt_tf32(a1v.x);
        As[ar + 64][akc + 1] = cvt_tf32(a1v.y);
        As[ar + 64][akc + 2] = cvt_tf32(a1v.z);
        As[ar + 64][akc + 3] = cvt_tf32(a1v.w);
        Bs[bk][bnc + 0] = cvt_tf32(bv.x);
        Bs[bk][bnc + 1] = cvt_tf32(bv.y);
        Bs[bk][bnc + 2] = cvt_tf32(bv.z);
        Bs[bk][bnc + 3] = cvt_tf32(bv.w);
        __syncthreads();

        // prefetch next K-tile while computing on this one
        if (k0 + GBK < K) {
            a0v = a0ok ? *(const float4*)&Arow0[k0 + GBK] : make_float4(0.f, 0.f, 0.f, 0.f);
            a1v = a1ok ? *(const float4*)&Arow1[k0 + GBK] : make_float4(0.f, 0.f, 0.f, 0.f);
            bv  = *(const float4*)&Brow[(size_t)(k0 + GBK) * N];
        }

#pragma unroll
        for (int ks = 0; ks < GBK; ks += 8) {
            unsigned af[2][4];
#pragma unroll
            for (int mi = 0; mi < 2; mi++) {
                int r = wm * 32 + mi * 16 + (lane >> 2);
                int kk = ks + (lane & 3);
                af[mi][0] = As[r][kk];
                af[mi][1] = As[r + 8][kk];
                af[mi][2] = As[r][kk + 4];
                af[mi][3] = As[r + 8][kk + 4];
            }
#pragma unroll
            for (int nj = 0; nj < 4; nj++) {
                int c = wn * 32 + nj * 8 + (lane >> 2);
                unsigned b0 = Bs[ks + (lane & 3)][c];
                unsigned b1 = Bs[ks + (lane & 3) + 4][c];
                mma_tf32(acc[0][nj], af[0], b0, b1);
                mma_tf32(acc[1][nj], af[1], b0, b1);
            }
        }
    }

    // store C
#pragma unroll
    for (int mi = 0; mi < 2; mi++) {
#pragma unroll
        for (int nj = 0; nj < 4; nj++) {
            int r0 = bm + wm * 32 + mi * 16 + (lane >> 2);
            int cc = bn + wn * 32 + nj * 8 + (lane & 3) * 2;
            if (r0 < M)
                *(float2*)&C[(size_t)r0 * N + cc] = make_float2(acc[mi][nj][0], acc[mi][nj][1]);
            if (r0 + 8 < M)
                *(float2*)&C[(size_t)(r0 + 8) * N + cc] = make_float2(acc[mi][nj][2], acc[mi][nj][3]);
        }
    }

    // fused attention dot products: per-row sums over this block's 64 columns
    if (att_src) {
        float ps[2][2] = {{0.f, 0.f}, {0.f, 0.f}};
        float pd[2][2] = {{0.f, 0.f}, {0.f, 0.f}};
#pragma unroll
        for (int nj = 0; nj < 4; nj++) {
            int c = bn + wn * 32 + nj * 8 + (lane & 3) * 2;
            float s0 = att_src[c], s1 = att_src[c + 1];
            float d0 = att_dst[c], d1 = att_dst[c + 1];
#pragma unroll
            for (int mi = 0; mi < 2; mi++) {
                ps[mi][0] += acc[mi][nj][0] * s0 + acc[mi][nj][1] * s1;
                ps[mi][1] += acc[mi][nj][2] * s0 + acc[mi][nj][3] * s1;
                pd[mi][0] += acc[mi][nj][0] * d0 + acc[mi][nj][1] * d1;
                pd[mi][1] += acc[mi][nj][2] * d0 + acc[mi][nj][3] * d1;
            }
        }
        // reduce across the 4 lanes of each row group (lane&3 = 0..3)
#pragma unroll
        for (int o = 1; o <= 2; o <<= 1) {
#pragma unroll
            for (int mi = 0; mi < 2; mi++)
#pragma unroll
                for (int hf = 0; hf < 2; hf++) {
                    ps[mi][hf] += __shfl_xor_sync(0xffffffffu, ps[mi][hf], o);
                    pd[mi][hf] += __shfl_xor_sync(0xffffffffu, pd[mi][hf], o);
                }
        }
        if ((lane & 3) == 0) {
#pragma unroll
            for (int mi = 0; mi < 2; mi++)
#pragma unroll
                for (int hf = 0; hf < 2; hf++) {
                    int rl = wm * 32 + mi * 16 + hf * 8 + (lane >> 2);
                    atomicAdd(&sdot_s[rl], ps[mi][hf]);
                    atomicAdd(&sdot_d[rl], pd[mi][hf]);
                }
        }
        __syncthreads();
        if (tid < GBM) {
            int r = bm + tid;
            if (r < M) {
                int col = bn / CC;   // head index (layer1) or 0 (layer2)
                asrc_out[(size_t)r * astride + col] = sdot_s[tid];
                adst_out[(size_t)r * astride + col] = sdot_d[tid];
            }
        }
    }
}

// ---------------- layer-1 fused gather: softmax + aggregate + bias + elu + residual ----------------
__global__ __launch_bounds__(256) void gat1_gather(const float* __restrict__ b1) {
    int d = (blockIdx.x * blockDim.x + threadIdx.x) >> 5;
    int lane = threadIdx.x & 31;
    if (d >= NN) return;
    const int beg = g_rowptr[d], end = g_rowptr[d + 1];

    const float ad0 = g_adst1[d * HH + 0];
    const float ad1 = g_adst1[d * HH + 1];
    const float ad2 = g_adst1[d * HH + 2];
    const float ad3 = g_adst1[d * HH + 3];

    float m0 = -CUDART_INF_F, m1 = m0, m2 = m0, m3 = m0;
    for (int i = beg + lane; i < end; i += 32) {
        int s = g_esrc[i];
        m0 = fmaxf(m0, lrelu(g_asrc1[s * HH + 0] + ad0));
        m1 = fmaxf(m1, lrelu(g_asrc1[s * HH + 1] + ad1));
        m2 = fmaxf(m2, lrelu(g_asrc1[s * HH + 2] + ad2));
        m3 = fmaxf(m3, lrelu(g_asrc1[s * HH + 3] + ad3));
    }
    m0 = wmax(m0); m1 = wmax(m1); m2 = wmax(m2); m3 = wmax(m3);

    float s0 = 0.f, s1 = 0.f, s2 = 0.f, s3 = 0.f;
    for (int i = beg + lane; i < end; i += 32) {
        int s = g_esrc[i];
        s0 += __expf(lrelu(g_asrc1[s * HH + 0] + ad0) - m0);
        s1 += __expf(lrelu(g_asrc1[s * HH + 1] + ad1) - m1);
        s2 += __expf(lrelu(g_asrc1[s * HH + 2] + ad2) - m2);
        s3 += __expf(lrelu(g_asrc1[s * HH + 3] + ad3) - m3);
    }
    s0 = wsum(s0); s1 = wsum(s1); s2 = wsum(s2); s3 = wsum(s3);
    const float inv0 = 1.f / (s0 + 1e-16f);
    const float inv1 = 1.f / (s1 + 1e-16f);
    const float inv2 = 1.f / (s2 + 1e-16f);
    const float inv3 = 1.f / (s3 + 1e-16f);

    float acc[8] = {0.f, 0.f, 0.f, 0.f, 0.f, 0.f, 0.f, 0.f};
    for (int i = beg; i < end; i++) {
        int s = g_esrc[i];
        float a0 = __expf(lrelu(g_asrc1[s * HH + 0] + ad0) - m0) * inv0;
        float a1 = __expf(lrelu(g_asrc1[s * HH + 1] + ad1) - m1) * inv1;
        float a2 = __expf(lrelu(g_asrc1[s * HH + 2] + ad2) - m2) * inv2;
        float a3 = __expf(lrelu(g_asrc1[s * HH + 3] + ad3) - m3) * inv3;
        const float* hrow = &g_hfeat1[(size_t)s * HC];
        acc[0] += hrow[lane +   0] * a0;
        acc[1] += hrow[lane +  32] * a0;
        acc[2] += hrow[lane +  64] * a1;
        acc[3] += hrow[lane +  96] * a1;
        acc[4] += hrow[lane + 128] * a2;
        acc[5] += hrow[lane + 160] * a2;
        acc[6] += hrow[lane + 192] * a3;
        acc[7] += hrow[lane + 224] * a3;
    }

    const size_t base = (size_t)d * HC;
#pragma unroll
    for (int k = 0; k < 8; k++) {
        int c = k * 32 + lane;
        float v = acc[k] + b1[c];
        v = (v > 0.f) ? v : (__expf(v) - 1.f);
        g_out1[base + c] = v + g_res1[base + c];
    }
}

// ---------------- layer-2 fused gather ----------------
__global__ __launch_bounds__(256) void gat2_gather(
    const float* __restrict__ b2, const float* __restrict__ wact,
    const float* __restrict__ bact, float* __restrict__ out)
{
    int d = (blockIdx.x * blockDim.x + threadIdx.x) >> 5;
    int lane = threadIdx.x & 31;
    if (d >= NN) return;
    const int beg = g_rowptr[d], end = g_rowptr[d + 1];
    const float add = g_adst2[d];

    float m = -CUDART_INF_F;
    for (int i = beg + lane; i < end; i += 32)
        m = fmaxf(m, lrelu(g_asrc2[g_esrc[i]] + add));
    m = wmax(m);

    float ssum = 0.f;
    for (int i = beg + lane; i < end; i += 32)
        ssum += __expf(lrelu(g_asrc2[g_esrc[i]] + add) - m);
    ssum = wsum(ssum);
    const float inv = 1.f / (ssum + 1e-16f);

    float acc0 = 0.f, acc1 = 0.f;
    for (int i = beg; i < end; i++) {
        int s = g_esrc[i];
        float alpha = __expf(lrelu(g_asrc2[s] + add) - m) * inv;
        if (lane == 0) out[OFF_ALPHA + g_eid[i]] = alpha;
        const float* hrow = &g_hfeat2[(size_t)s * CC];
        acc0 += hrow[lane]      * alpha;
        acc1 += hrow[lane + 32] * alpha;
    }

    const size_t base = (size_t)d * CC;
    float v0 = acc0 + b2[lane]      + g_res2[base + lane];
    float v1 = acc1 + b2[lane + 32] + g_res2[base + lane + 32];
    float ss = wsum(v0 * v0 + v1 * v1);
    float norm = fmaxf(sqrtf(ss), 1e-12f);
    float h0 = v0 / norm, h1 = v1 / norm;
    out[OFF_H2 + base + lane]      = h0;
    out[OFF_H2 + base + lane + 32] = h1;
    float dot = wsum(h0 * wact[lane] + h1 * wact[lane + 32]);
    if (lane == 0) out[OFF_LOGITS + d] = dot + bact[0];
}

// ---------------- argmax ----------------
__global__ void argmax_part(const float* __restrict__ out) {
    __shared__ float sv[256];
    __shared__ int   si[256];
    int t = threadIdx.x;
    int n = blockIdx.x * 256 + t;
    sv[t] = (n < NN) ? out[OFF_LOGITS + n] : -CUDART_INF_F;
    si[t] = n;
    __syncthreads();
    for (int s = 128; s > 0; s >>= 1) {
        if (t < s) {
            if (sv[t + s] > sv[t] || (sv[t + s] == sv[t] && si[t + s] < si[t])) {
                sv[t] = sv[t + s]; si[t] = si[t + s];
            }
        }
        __syncthreads();
    }
    if (t == 0) { g_pval[blockIdx.x] = sv[0]; g_pidx[blockIdx.x] = si[0]; }
}

__global__ void argmax_final(float* __restrict__ out) {
    __shared__ float sv[256];
    __shared__ int   si[256];
    int t = threadIdx.x;
    sv[t] = (t < NB_ARGMAX) ? g_pval[t] : -CUDART_INF_F;
    si[t] = (t < NB_ARGMAX) ? g_pidx[t] : 0x7fffffff;
    __syncthreads();
    for (int s = 128; s > 0; s >>= 1) {
        if (t < s) {
            if (sv[t + s] > sv[t] || (sv[t + s] == sv[t] && si[t + s] < si[t])) {
                sv[t] = sv[t + s]; si[t] = si[t + s];
            }
        }
        __syncthreads();
    }
    if (t == 0) out[OFF_ACTION] = (float)si[0];
}

// ---------------- launch ----------------
extern "C" void kernel_launch(void* const* d_in, const int* in_sizes, int n_in,
                              void* d_out, int out_size) {
    const float* x    = (const float*)d_in[0];
    const int*   ei   = (const int*)  d_in[1];
    const float* W1   = (const float*)d_in[2];
    const float* as1  = (const float*)d_in[3];
    const float* ad1  = (const float*)d_in[4];
    const float* b1   = (const float*)d_in[5];
    const float* W2   = (const float*)d_in[6];
    const float* as2  = (const float*)d_in[7];
    const float* ad2  = (const float*)d_in[8];
    const float* b2   = (const float*)d_in[9];
    const float* Wr1  = (const float*)d_in[10];
    const float* Wr2  = (const float*)d_in[11];
    const float* wact = (const float*)d_in[12];
    const float* bact = (const float*)d_in[13];
    float* out = (float*)d_out;

    void *p_hf1, *p_r1, *p_o1, *p_hf2, *p_r2, *p_as1, *p_ad1, *p_as2, *p_ad2;
    cudaGetSymbolAddress(&p_hf1, g_hfeat1);
    cudaGetSymbolAddress(&p_r1,  g_res1);
    cudaGetSymbolAddress(&p_o1,  g_out1);
    cudaGetSymbolAddress(&p_hf2, g_hfeat2);
    cudaGetSymbolAddress(&p_r2,  g_res2);
    cudaGetSymbolAddress(&p_as1, g_asrc1);
    cudaGetSymbolAddress(&p_ad1, g_adst1);
    cudaGetSymbolAddress(&p_as2, g_asrc2);
    cudaGetSymbolAddress(&p_ad2, g_adst2);

    // CSR build (shared by both layers)
    init_kernel<<<(NN + 255) / 256, 256>>>();
    csr_count<<<(ETOT + 255) / 256, 256>>>(ei);
    csr_scan<<<1, 1024>>>();
    csr_scatter<<<(ETOT + 255) / 256, 256>>>(ei);

    const int MB = (NN + GBM - 1) / GBM;

    // layer 1: hfeat1 GEMM fuses the per-head attention dots
    gemm_tf32<<<dim3(HC / GBN, MB), 256>>>(x, W1, (float*)p_hf1, NN, HC, FF,
                                           as1, ad1, (float*)p_as1, (float*)p_ad1, HH);
    gemm_tf32<<<dim3(HC / GBN, MB), 256>>>(x, Wr1, (float*)p_r1, NN, HC, FF,
                                           nullptr, nullptr, nullptr, nullptr, 0);
    gat1_gather<<<(NN * 32 + 255) / 256, 256>>>(b1);

    // layer 2: hfeat2 GEMM fuses the attention dots (single head)
    gemm_tf32<<<dim3(CC / GBN, MB), 256>>>((const float*)p_o1, W2, (float*)p_hf2, NN, CC, HC,
                                           as2, ad2, (float*)p_as2, (float*)p_ad2, 1);
    gemm_tf32<<<dim3(CC / GBN, MB), 256>>>((const float*)p_o1, Wr2, (float*)p_r2, NN, CC, HC,
                                           nullptr, nullptr, nullptr, nullptr, 0);
    gat2_gather<<<(NN * 32 + 255) / 256, 256>>>(b2, wact, bact, out);

    argmax_part<<<NB_ARGMAX, 256>>>(out);
    argmax_final<<<1, 256>>>(out);
}